// round 3
// baseline (speedup 1.0000x reference)
#include <cuda_runtime.h>
#include <math.h>
#include <stdint.h>

#define Bb_ 64
#define Tt_ 4096
#define Dd_ 256
#define Hh_ 256
#define Oo_ 256

// Scratch (device globals: no allocation allowed in kernel_launch)
__device__ float g_xp[(size_t)Tt_ * Bb_ * Hh_];   // (T, B, H)
__device__ float g_hs[(size_t)Bb_ * Tt_ * Hh_];   // (B, T, H)

// ---------------------------------------------------------------------------
// SGEMM: C = A(MxK) @ W(KxN) + bias, K=N=256.  (unchanged from round 2)
// mode 0: C[row*N + n]                     (out = hs @ W_hy)
// mode 1: C[((row%T)*B + row/T)*N + n]     (xp, stored (T,B,H))
// ---------------------------------------------------------------------------
__global__ void __launch_bounds__(256) sgemm_bias(
    const float* __restrict__ A, const float* __restrict__ W,
    const float* __restrict__ bias, float* __restrict__ C,
    int M, int mode)
{
    const int K = 256, N = 256;
    __shared__ float As[2][8][128];
    __shared__ float Bs[2][8][128];

    int tid = threadIdx.x;
    int rowTile = blockIdx.y;
    int colTile = blockIdx.x;

    const float* Ab = A + (size_t)rowTile * 128 * K;
    const float* Wb = W + colTile * 128;

    int aRow = tid >> 1;
    int aCol = (tid & 1) * 4;
    int bRow = tid >> 5;
    int bCol = (tid & 31) * 4;

    int ty = tid >> 4;
    int tx = tid & 15;

    float acc[8][8];
#pragma unroll
    for (int i = 0; i < 8; i++)
#pragma unroll
        for (int j = 0; j < 8; j++) acc[i][j] = 0.f;

    float4 aReg = *(const float4*)(Ab + (size_t)aRow * K + aCol);
    float4 bReg = *(const float4*)(Wb + (size_t)bRow * N + bCol);
    As[0][aCol + 0][aRow] = aReg.x;
    As[0][aCol + 1][aRow] = aReg.y;
    As[0][aCol + 2][aRow] = aReg.z;
    As[0][aCol + 3][aRow] = aReg.w;
    *(float4*)&Bs[0][bRow][bCol] = bReg;
    __syncthreads();

    const int nK = K / 8;
    for (int kt = 0; kt < nK; kt++) {
        int cur = kt & 1, nxt = cur ^ 1;
        if (kt + 1 < nK) {
            aReg = *(const float4*)(Ab + (size_t)aRow * K + (kt + 1) * 8 + aCol);
            bReg = *(const float4*)(Wb + (size_t)((kt + 1) * 8 + bRow) * N + bCol);
        }
#pragma unroll
        for (int k = 0; k < 8; k++) {
            float a[8], bv[8];
            *(float4*)&a[0]  = *(const float4*)&As[cur][k][ty * 4];
            *(float4*)&a[4]  = *(const float4*)&As[cur][k][ty * 4 + 64];
            *(float4*)&bv[0] = *(const float4*)&Bs[cur][k][tx * 4];
            *(float4*)&bv[4] = *(const float4*)&Bs[cur][k][tx * 4 + 64];
#pragma unroll
            for (int i = 0; i < 8; i++)
#pragma unroll
                for (int j = 0; j < 8; j++)
                    acc[i][j] = fmaf(a[i], bv[j], acc[i][j]);
        }
        if (kt + 1 < nK) {
            As[nxt][aCol + 0][aRow] = aReg.x;
            As[nxt][aCol + 1][aRow] = aReg.y;
            As[nxt][aCol + 2][aRow] = aReg.z;
            As[nxt][aCol + 3][aRow] = aReg.w;
            *(float4*)&Bs[nxt][bRow][bCol] = bReg;
        }
        __syncthreads();
    }

#pragma unroll
    for (int i = 0; i < 8; i++) {
        int lm = (i < 4) ? (ty * 4 + i) : (64 + ty * 4 + (i - 4));
        long gm = (long)rowTile * 128 + lm;
        size_t rowOff;
        if (mode == 0) {
            rowOff = (size_t)gm * N;
        } else {
            int t  = (int)(gm % Tt_);
            int bb = (int)(gm / Tt_);
            rowOff = ((size_t)t * Bb_ + bb) * N;
        }
#pragma unroll
        for (int j = 0; j < 8; j++) {
            int ln = (j < 4) ? (tx * 4 + j) : (64 + tx * 4 + (j - 4));
            int gn = colTile * 128 + ln;
            C[rowOff + gn] = acc[i][j] + bias[gn];
        }
    }
}

// ---------------------------------------------------------------------------
// Cluster scan: 2 CTAs per chain (128 CTAs, one wave). Each CTA owns 128
// output columns; 2 threads per column (lane l and l^16 of the same warp),
// each holding 64 k-pairs of W_hh ENTIRELY in registers (128 regs), split
// 32 local-half + 32 remote-half pairs so local FMAs overlap the DSMEM
// flight of the peer CTA's h-half. Split mbarriers per (buffer, half).
// ---------------------------------------------------------------------------

#define FMA2(acc, h, w) \
    asm("fma.rn.f32x2 %0, %1, %2, %0;" : "+l"(acc) : "l"(h), "l"(w))

__device__ __forceinline__ unsigned long long pack2(float lo, float hi) {
    unsigned long long v;
    asm("mov.b64 %0, {%1, %2};" : "=l"(v) : "f"(lo), "f"(hi));
    return v;
}
__device__ __forceinline__ float sum2(unsigned long long v) {
    float lo, hi;
    asm("mov.b64 {%0, %1}, %2;" : "=f"(lo), "=f"(hi) : "l"(v));
    return lo + hi;
}
__device__ __forceinline__ uint32_t smem_u32(const void* p) {
    uint32_t a;
    asm("{ .reg .u64 t; cvta.to.shared.u64 t, %1; cvt.u32.u64 %0, t; }"
        : "=r"(a) : "l"(p));
    return a;
}
__device__ __forceinline__ uint32_t mapa_u32(uint32_t laddr, uint32_t peer) {
    uint32_t r;
    asm("mapa.shared::cluster.u32 %0, %1, %2;" : "=r"(r) : "r"(laddr), "r"(peer));
    return r;
}
__device__ __forceinline__ void mbar_init(uint32_t addr, uint32_t cnt) {
    asm volatile("mbarrier.init.shared.b64 [%0], %1;" :: "r"(addr), "r"(cnt) : "memory");
}
__device__ __forceinline__ void mbar_arrive_local(uint32_t addr) {
    asm volatile("mbarrier.arrive.release.cta.shared::cta.b64 _, [%0];"
                 :: "r"(addr) : "memory");
}
__device__ __forceinline__ void mbar_arrive_remote(uint32_t raddr) {
    asm volatile("mbarrier.arrive.release.cluster.shared::cluster.b64 _, [%0];"
                 :: "r"(raddr) : "memory");
}
__device__ __forceinline__ void st_remote_f32(uint32_t raddr, float v) {
    asm volatile("st.shared::cluster.f32 [%0], %1;" :: "r"(raddr), "f"(v) : "memory");
}
__device__ __forceinline__ void mbar_wait_cta(uint32_t addr, uint32_t parity) {
    asm volatile(
        "{\n\t"
        ".reg .pred P;\n\t"
        "WL%=:\n\t"
        "mbarrier.try_wait.parity.acquire.cta.shared::cta.b64 P, [%0], %1, 0x989680;\n\t"
        "@P bra WD%=;\n\t"
        "bra WL%=;\n\t"
        "WD%=:\n\t"
        "}" :: "r"(addr), "r"(parity) : "memory");
}
__device__ __forceinline__ void mbar_wait_cluster(uint32_t addr, uint32_t parity) {
    asm volatile(
        "{\n\t"
        ".reg .pred P;\n\t"
        "WL%=:\n\t"
        "mbarrier.try_wait.parity.acquire.cluster.shared::cta.b64 P, [%0], %1, 0x989680;\n\t"
        "@P bra WD%=;\n\t"
        "bra WL%=;\n\t"
        "WD%=:\n\t"
        "}" :: "r"(addr), "r"(parity) : "memory");
}

__global__ void __launch_bounds__(256, 1) __cluster_dims__(2, 1, 1)
rnn_scan_cluster(
    const float* __restrict__ xp,   // (T, B, H)
    const float* __restrict__ Whh,  // (H, H) [k][j]
    const float* __restrict__ h0,   // (B, H)
    float* __restrict__ hs,         // (B, T, H)
    float* __restrict__ hfin)       // (B, H)
{
    __shared__ float hbuf[2][Hh_];
    __shared__ __align__(8) unsigned long long barL[2];  // local half of buf i ready
    __shared__ __align__(8) unsigned long long barR[2];  // remote half of buf i ready

    const int b    = blockIdx.x >> 1;
    const int r    = blockIdx.x & 1;          // cluster rank
    const int tid  = threadIdx.x;
    const int w    = tid >> 5;
    const int lane = tid & 31;
    const int khalf = lane >> 4;              // which k-quarter pair owner
    const int jl   = w * 16 + (lane & 15);    // local column 0..127
    const int J    = r * 128 + jl;            // global column

    // k ranges: local half = columns this CTA produces = [r*128, r*128+128)
    const int kbaseL = r * 128 + khalf * 64;          // 32 pairs
    const int kbaseR = (1 - r) * 128 + khalf * 64;    // 32 pairs

    // barrier / remote addresses
    const uint32_t u_barL0 = smem_u32(&barL[0]);
    const uint32_t u_barL1 = smem_u32(&barL[1]);
    const uint32_t u_barR0 = smem_u32(&barR[0]);
    const uint32_t u_barR1 = smem_u32(&barR[1]);
    const uint32_t u_hbuf  = smem_u32(&hbuf[0][0]);
    const uint32_t peer    = (uint32_t)(1 - r);
    const uint32_t ru_hbuf = mapa_u32(u_hbuf, peer);
    const uint32_t ru_barR0 = mapa_u32(u_barR0, peer);
    const uint32_t ru_barR1 = mapa_u32(u_barR1, peer);

    if (tid == 0) {
        mbar_init(u_barL0, 128);
        mbar_init(u_barL1, 128);
        mbar_init(u_barR0, 128);
        mbar_init(u_barR1, 128);
    }

    // register-resident weights: 32 local-half + 32 remote-half pairs
    unsigned long long wrL[32], wrR[32];
#pragma unroll
    for (int p = 0; p < 32; p++) {
        int k = kbaseL + 2 * p;
        wrL[p] = pack2(Whh[(size_t)k * Hh_ + J], Whh[(size_t)(k + 1) * Hh_ + J]);
    }
#pragma unroll
    for (int p = 0; p < 32; p++) {
        int k = kbaseR + 2 * p;
        wrR[p] = pack2(Whh[(size_t)k * Hh_ + J], Whh[(size_t)(k + 1) * Hh_ + J]);
    }

    // initial h: each CTA fills its FULL local hbuf[0] from h0 (no comms)
    hbuf[0][tid] = h0[b * Hh_ + tid];
    __syncthreads();
    // barriers + initial buffer visible cluster-wide before any remote traffic
    asm volatile("barrier.cluster.arrive.aligned;" ::: "memory");
    asm volatile("barrier.cluster.wait.aligned;"   ::: "memory");

    // xp prefetch (producers only: lane < 16)
    const bool prod = (lane < 16);
    float xpc = 0.f, xpn = 0.f;
    if (prod) {
        xpc = __ldcs(&xp[((size_t)0 * Bb_ + b) * Hh_ + J]);
        xpn = __ldcs(&xp[((size_t)1 * Bb_ + b) * Hh_ + J]);
    }

    const size_t hs_base = ((size_t)b * Tt_) * Hh_ + J;
    int phL0 = 0, phL1 = 0, phR0 = 0, phR1 = 0;
    float hlast = 0.f;

    const int li = kbaseL >> 2;   // ulonglong2 index base into hbuf row
    const int ri = kbaseR >> 2;

    for (int t = 0; t < Tt_; t++) {
        const int pb = t & 1;
        const int nb = pb ^ 1;

        // wait local half of buffer pb (fast path), skip at t=0
        if (t > 0) {
            if (pb == 0) { mbar_wait_cta(u_barL0, phL0); phL0 ^= 1; }
            else         { mbar_wait_cta(u_barL1, phL1); phL1 ^= 1; }
        }

        const ulonglong2* h2 = (const ulonglong2*)(&hbuf[pb][0]);

        unsigned long long a0 = 0ull, a1 = 0ull;
#pragma unroll
        for (int q = 0; q < 16; q++) {          // local-half 32 pairs
            ulonglong2 hv = h2[li + q];
            FMA2(a0, hv.x, wrL[2 * q]);
            FMA2(a1, hv.y, wrL[2 * q + 1]);
        }

        // wait remote half of buffer pb (overlapped with FMAs above)
        if (t > 0) {
            if (pb == 0) { mbar_wait_cluster(u_barR0, phR0); phR0 ^= 1; }
            else         { mbar_wait_cluster(u_barR1, phR1); phR1 ^= 1; }
        }

#pragma unroll
        for (int q = 0; q < 16; q++) {          // remote-half 32 pairs
            ulonglong2 hv = h2[ri + q];
            FMA2(a0, hv.x, wrR[2 * q]);
            FMA2(a1, hv.y, wrR[2 * q + 1]);
        }

        float v = sum2(a0) + sum2(a1);
        v += __shfl_xor_sync(0xffffffffu, v, 16);

        if (prod) {
            float h = tanhf(v + xpc);
            hs[hs_base + (size_t)t * Hh_] = h;
            hlast = h;
            if (t + 1 < Tt_) {
                // local publish + arrive
                hbuf[nb][J] = h;
                // remote publish + arrive (release.cluster orders the st)
                st_remote_f32(ru_hbuf + (uint32_t)(nb * Hh_ + J) * 4u, h);
                if (nb == 0) {
                    mbar_arrive_local(u_barL0);
                    mbar_arrive_remote(ru_barR0);
                } else {
                    mbar_arrive_local(u_barL1);
                    mbar_arrive_remote(ru_barR1);
                }
            }
            xpc = xpn;
            if (t + 2 < Tt_)
                xpn = __ldcs(&xp[((size_t)(t + 2) * Bb_ + b) * Hh_ + J]);
        }
    }

    if (prod) hfin[b * Hh_ + J] = hlast;

    // no CTA may exit while peer remote ops could be in flight
    asm volatile("barrier.cluster.arrive.aligned;" ::: "memory");
    asm volatile("barrier.cluster.wait.aligned;"   ::: "memory");
}

// ---------------------------------------------------------------------------
// Launch
// ---------------------------------------------------------------------------
extern "C" void kernel_launch(void* const* d_in, const int* in_sizes, int n_in,
                              void* d_out, int out_size)
{
    const float* x    = (const float*)d_in[0];  // (B,T,D)
    const float* h0   = (const float*)d_in[1];  // (B,H)
    const float* W_xh = (const float*)d_in[2];  // (D,H)
    const float* W_hh = (const float*)d_in[3];  // (H,H)
    const float* b_h  = (const float*)d_in[4];  // (H)
    const float* W_hy = (const float*)d_in[5];  // (H,O)
    const float* b_y  = (const float*)d_in[6];  // (O)

    float* out  = (float*)d_out;                           // (B,T,O)
    float* hfin = out + (size_t)Bb_ * Tt_ * Oo_;           // (B,H)

    void* xp_ptr = nullptr;
    void* hs_ptr = nullptr;
    cudaGetSymbolAddress(&xp_ptr, g_xp);
    cudaGetSymbolAddress(&hs_ptr, g_hs);

    const int M = Bb_ * Tt_;            // 262144 rows
    dim3 gemmGrid(2, M / 128);

    // 1) xp = x @ W_xh + b_h   -> (T,B,H)
    sgemm_bias<<<gemmGrid, 256>>>(x, W_xh, b_h, (float*)xp_ptr, M, 1);

    // 2) cluster scan -> hs (B,T,H), h_final
    rnn_scan_cluster<<<2 * Bb_, 256>>>((const float*)xp_ptr, W_hh, h0,
                                       (float*)hs_ptr, hfin);

    // 3) out = hs @ W_hy + b_y -> (B,T,O)
    sgemm_bias<<<gemmGrid, 256>>>((const float*)hs_ptr, W_hy, b_y, out, M, 0);
}

// round 5
// speedup vs baseline: 1.6954x; 1.6954x over previous
#include <cuda_runtime.h>
#include <math.h>
#include <stdint.h>

#define Bb_ 64
#define Tt_ 4096
#define Dd_ 256
#define Hh_ 256
#define Oo_ 256

// Scratch (device globals: no allocation allowed in kernel_launch)
__device__ float g_xp[(size_t)Tt_ * Bb_ * Hh_];   // (T, B, H)
__device__ float g_hs[(size_t)Bb_ * Tt_ * Hh_];   // (B, T, H)

// ---------------------------------------------------------------------------
// SGEMM: C = A(MxK) @ W(KxN) + bias, K=N=256.
// mode 0: C[row*N + n]                     (out = hs @ W_hy)
// mode 1: C[((row%T)*B + row/T)*N + n]     (xp, stored (T,B,H))
// R5: __launch_bounds__(256, 2) to get 2 CTAs/SM (occupancy was 24.5%).
// ---------------------------------------------------------------------------
__global__ void __launch_bounds__(256, 2) sgemm_bias(
    const float* __restrict__ A, const float* __restrict__ W,
    const float* __restrict__ bias, float* __restrict__ C,
    int M, int mode)
{
    const int K = 256, N = 256;
    __shared__ float As[2][8][128];
    __shared__ float Bs[2][8][128];

    int tid = threadIdx.x;
    int rowTile = blockIdx.y;
    int colTile = blockIdx.x;

    const float* Ab = A + (size_t)rowTile * 128 * K;
    const float* Wb = W + colTile * 128;

    int aRow = tid >> 1;
    int aCol = (tid & 1) * 4;
    int bRow = tid >> 5;
    int bCol = (tid & 31) * 4;

    int ty = tid >> 4;
    int tx = tid & 15;

    float acc[8][8];
#pragma unroll
    for (int i = 0; i < 8; i++)
#pragma unroll
        for (int j = 0; j < 8; j++) acc[i][j] = 0.f;

    float4 aReg = *(const float4*)(Ab + (size_t)aRow * K + aCol);
    float4 bReg = *(const float4*)(Wb + (size_t)bRow * N + bCol);
    As[0][aCol + 0][aRow] = aReg.x;
    As[0][aCol + 1][aRow] = aReg.y;
    As[0][aCol + 2][aRow] = aReg.z;
    As[0][aCol + 3][aRow] = aReg.w;
    *(float4*)&Bs[0][bRow][bCol] = bReg;
    __syncthreads();

    const int nK = K / 8;
    for (int kt = 0; kt < nK; kt++) {
        int cur = kt & 1, nxt = cur ^ 1;
        if (kt + 1 < nK) {
            aReg = *(const float4*)(Ab + (size_t)aRow * K + (kt + 1) * 8 + aCol);
            bReg = *(const float4*)(Wb + (size_t)((kt + 1) * 8 + bRow) * N + bCol);
        }
#pragma unroll
        for (int k = 0; k < 8; k++) {
            float a[8], bv[8];
            *(float4*)&a[0]  = *(const float4*)&As[cur][k][ty * 4];
            *(float4*)&a[4]  = *(const float4*)&As[cur][k][ty * 4 + 64];
            *(float4*)&bv[0] = *(const float4*)&Bs[cur][k][tx * 4];
            *(float4*)&bv[4] = *(const float4*)&Bs[cur][k][tx * 4 + 64];
#pragma unroll
            for (int i = 0; i < 8; i++)
#pragma unroll
                for (int j = 0; j < 8; j++)
                    acc[i][j] = fmaf(a[i], bv[j], acc[i][j]);
        }
        if (kt + 1 < nK) {
            As[nxt][aCol + 0][aRow] = aReg.x;
            As[nxt][aCol + 1][aRow] = aReg.y;
            As[nxt][aCol + 2][aRow] = aReg.z;
            As[nxt][aCol + 3][aRow] = aReg.w;
            *(float4*)&Bs[nxt][bRow][bCol] = bReg;
        }
        __syncthreads();
    }

#pragma unroll
    for (int i = 0; i < 8; i++) {
        int lm = (i < 4) ? (ty * 4 + i) : (64 + ty * 4 + (i - 4));
        long gm = (long)rowTile * 128 + lm;
        size_t rowOff;
        if (mode == 0) {
            rowOff = (size_t)gm * N;
        } else {
            int t  = (int)(gm % Tt_);
            int bb = (int)(gm / Tt_);
            rowOff = ((size_t)t * Bb_ + bb) * N;
        }
#pragma unroll
        for (int j = 0; j < 8; j++) {
            int ln = (j < 4) ? (tx * 4 + j) : (64 + tx * 4 + (j - 4));
            int gn = colTile * 128 + ln;
            C[rowOff + gn] = acc[i][j] + bias[gn];
        }
    }
}

// ---------------------------------------------------------------------------
// K-split cluster scan. 2 CTAs per chain (128 CTAs, one wave).
// CTA r owns k-rows AND output columns [128r, 128r+128). Each thread computes
// the partial sum for ONE column c=tid over the local 128 k-rows (64 weight
// pairs fully in registers, h-half broadcast from local smem). Only 128
// partial floats cross the cluster per step, via st.async + tx mbarrier.
// ---------------------------------------------------------------------------

#define FMA2(acc, h, w) \
    asm("fma.rn.f32x2 %0, %1, %2, %0;" : "+l"(acc) : "l"(h), "l"(w))

__device__ __forceinline__ unsigned long long pack2(float lo, float hi) {
    unsigned long long v;
    asm("mov.b64 %0, {%1, %2};" : "=l"(v) : "f"(lo), "f"(hi));
    return v;
}
__device__ __forceinline__ float sum2(unsigned long long v) {
    float lo, hi;
    asm("mov.b64 {%0, %1}, %2;" : "=f"(lo), "=f"(hi) : "l"(v));
    return lo + hi;
}
__device__ __forceinline__ uint32_t smem_u32(const void* p) {
    uint32_t a;
    asm("{ .reg .u64 t; cvta.to.shared.u64 t, %1; cvt.u32.u64 %0, t; }"
        : "=r"(a) : "l"(p));
    return a;
}
__device__ __forceinline__ uint32_t mapa_u32(uint32_t laddr, uint32_t peer) {
    uint32_t r;
    asm("mapa.shared::cluster.u32 %0, %1, %2;" : "=r"(r) : "r"(laddr), "r"(peer));
    return r;
}
__device__ __forceinline__ void mbar_init(uint32_t addr, uint32_t cnt) {
    asm volatile("mbarrier.init.shared.b64 [%0], %1;" :: "r"(addr), "r"(cnt) : "memory");
}
__device__ __forceinline__ void mbar_expect_tx(uint32_t addr, uint32_t bytes) {
    asm volatile("mbarrier.arrive.expect_tx.shared.b64 _, [%0], %1;"
                 :: "r"(addr), "r"(bytes) : "memory");
}
// remote store with transaction accounting on the PEER's mbarrier
__device__ __forceinline__ void st_async_f32(uint32_t raddr, float v, uint32_t rbar) {
    asm volatile(
        "st.async.shared::cluster.mbarrier::complete_tx::bytes.b32 [%0], %1, [%2];"
        :: "r"(raddr), "r"(__float_as_uint(v)), "r"(rbar) : "memory");
}
__device__ __forceinline__ void mbar_wait_cluster(uint32_t addr, uint32_t parity) {
    asm volatile(
        "{\n\t"
        ".reg .pred P;\n\t"
        "WL%=:\n\t"
        "mbarrier.try_wait.parity.acquire.cluster.shared::cta.b64 P, [%0], %1, 0x989680;\n\t"
        "@P bra WD%=;\n\t"
        "bra WL%=;\n\t"
        "WD%=:\n\t"
        "}" :: "r"(addr), "r"(parity) : "memory");
}

__global__ void __launch_bounds__(256, 1) __cluster_dims__(2, 1, 1)
rnn_scan_ksplit(
    const float* __restrict__ xp,   // (T, B, H)
    const float* __restrict__ Whh,  // (H, H) [k][j]
    const float* __restrict__ h0,   // (B, H)
    float* __restrict__ hs,         // (B, T, H)
    float* __restrict__ hfin)       // (B, H)
{
    __shared__ float hbuf[2][128];                         // local h half
    __shared__ float rbuf[2][128];                         // received partials
    __shared__ __align__(8) unsigned long long bar[2];

    const int b   = blockIdx.x >> 1;
    const int r   = blockIdx.x & 1;                        // cluster rank
    const int tid = threadIdx.x;
    const int c   = tid;                                   // global column
    const int ci  = c & 127;                               // index within a half
    const bool own = ((c >> 7) == r);                      // finalized locally?
    const int kbase = r * 128;                             // local k-half base

    const uint32_t u_bar0 = smem_u32(&bar[0]);
    const uint32_t u_bar1 = smem_u32(&bar[1]);
    const uint32_t u_rbuf = smem_u32(&rbuf[0][0]);
    const uint32_t peer   = (uint32_t)(1 - r);
    const uint32_t ru_rbuf = mapa_u32(u_rbuf, peer);
    const uint32_t ru_bar0 = mapa_u32(u_bar0, peer);
    const uint32_t ru_bar1 = mapa_u32(u_bar1, peer);

    if (tid == 0) {
        mbar_init(u_bar0, 1);
        mbar_init(u_bar1, 1);
        // pre-arm both buffers for steps t=0 and t=1
        mbar_expect_tx(u_bar0, 128 * 4);
        mbar_expect_tx(u_bar1, 128 * 4);
    }

    // 64 register-resident weight pairs: W_hh[kbase .. kbase+127][c]
    unsigned long long wr[64];
#pragma unroll
    for (int p = 0; p < 64; p++) {
        int k = kbase + 2 * p;
        wr[p] = pack2(Whh[(size_t)k * Hh_ + c], Whh[(size_t)(k + 1) * Hh_ + c]);
    }

    // initial h: local half only
    if (tid < 128) hbuf[0][tid] = h0[b * Hh_ + kbase + tid];
    __syncthreads();
    // barriers + initial state visible cluster-wide before any st.async
    asm volatile("barrier.cluster.arrive.aligned;" ::: "memory");
    asm volatile("barrier.cluster.wait.aligned;"   ::: "memory");

    // xp prefetch (finalizers only)
    float xpc = 0.f, xpn = 0.f;
    if (own) {
        xpc = __ldcs(&xp[((size_t)0 * Bb_ + b) * Hh_ + c]);
        xpn = __ldcs(&xp[((size_t)1 * Bb_ + b) * Hh_ + c]);
    }

    const size_t hs_base = ((size_t)b * Tt_) * Hh_ + c;
    float hlast = 0.f;

    for (int t = 0; t < Tt_; t++) {
        const int pb = t & 1;
        const int nb = pb ^ 1;

        // partial[c] = sum over the local 128 k-rows (h broadcast from smem)
        const ulonglong2* h2 = (const ulonglong2*)(&hbuf[pb][0]);  // 32 entries
        unsigned long long a0 = 0ull, a1 = 0ull, a2 = 0ull, a3 = 0ull;
#pragma unroll
        for (int q = 0; q < 16; q++) {
            ulonglong2 hv0 = h2[2 * q];          // h floats 8q .. 8q+3
            ulonglong2 hv1 = h2[2 * q + 1];      // h floats 8q+4 .. 8q+7
            FMA2(a0, hv0.x, wr[4 * q + 0]);
            FMA2(a1, hv0.y, wr[4 * q + 1]);
            FMA2(a2, hv1.x, wr[4 * q + 2]);
            FMA2(a3, hv1.y, wr[4 * q + 3]);
        }
        float part = (sum2(a0) + sum2(a1)) + (sum2(a2) + sum2(a3));

        if (!own) {
            // ship partial to the peer (its finalizer for column c)
            uint32_t rb = (pb == 0) ? ru_bar0 : ru_bar1;
            st_async_f32(ru_rbuf + (uint32_t)(pb * 128 + ci) * 4u, part, rb);
        } else {
            // wait for peer's 128 partials (tx-complete flips parity)
            uint32_t ub = (pb == 0) ? u_bar0 : u_bar1;
            mbar_wait_cluster(ub, (t >> 1) & 1);
            // re-arm this buffer for step t+2 (one arrive, 512 tx bytes)
            if (ci == 0 && t + 2 < Tt_) mbar_expect_tx(ub, 128 * 4);

            float h = tanhf(part + rbuf[pb][ci] + xpc);
            hs[hs_base + (size_t)t * Hh_] = h;
            hlast = h;
            hbuf[nb][ci] = h;

            xpc = xpn;
            if (t + 2 < Tt_)
                xpn = __ldcs(&xp[((size_t)(t + 2) * Bb_ + b) * Hh_ + c]);
        }
        __syncthreads();   // hbuf[nb] visible to all local threads
    }

    if (own) hfin[b * Hh_ + c] = hlast;

    // no CTA exits while peer traffic could be in flight
    asm volatile("barrier.cluster.arrive.aligned;" ::: "memory");
    asm volatile("barrier.cluster.wait.aligned;"   ::: "memory");
}

// ---------------------------------------------------------------------------
// Launch
// ---------------------------------------------------------------------------
extern "C" void kernel_launch(void* const* d_in, const int* in_sizes, int n_in,
                              void* d_out, int out_size)
{
    const float* x    = (const float*)d_in[0];  // (B,T,D)
    const float* h0   = (const float*)d_in[1];  // (B,H)
    const float* W_xh = (const float*)d_in[2];  // (D,H)
    const float* W_hh = (const float*)d_in[3];  // (H,H)
    const float* b_h  = (const float*)d_in[4];  // (H)
    const float* W_hy = (const float*)d_in[5];  // (H,O)
    const float* b_y  = (const float*)d_in[6];  // (O)

    float* out  = (float*)d_out;                           // (B,T,O)
    float* hfin = out + (size_t)Bb_ * Tt_ * Oo_;           // (B,H)

    void* xp_ptr = nullptr;
    void* hs_ptr = nullptr;
    cudaGetSymbolAddress(&xp_ptr, g_xp);
    cudaGetSymbolAddress(&hs_ptr, g_hs);

    const int M = Bb_ * Tt_;            // 262144 rows
    dim3 gemmGrid(2, M / 128);

    // 1) xp = x @ W_xh + b_h   -> (T,B,H)
    sgemm_bias<<<gemmGrid, 256>>>(x, W_xh, b_h, (float*)xp_ptr, M, 1);

    // 2) k-split cluster scan -> hs (B,T,H), h_final
    rnn_scan_ksplit<<<2 * Bb_, 256>>>((const float*)xp_ptr, W_hh, h0,
                                      (float*)hs_ptr, hfin);

    // 3) out = hs @ W_hy + b_y -> (B,T,O)
    sgemm_bias<<<gemmGrid, 256>>>((const float*)hs_ptr, W_hy, b_y, out, M, 0);
}

// round 7
// speedup vs baseline: 2.0420x; 1.2044x over previous
#include <cuda_runtime.h>
#include <cuda_bf16.h>
#include <math.h>
#include <stdint.h>

#define Bb_ 64
#define Tt_ 4096
#define Dd_ 256
#define Hh_ 256
#define Oo_ 256

// Scratch (device globals: no allocation allowed in kernel_launch)
__device__ float g_xp[(size_t)Tt_ * Bb_ * Hh_];   // (T, B, H)
__device__ float g_hs[(size_t)Bb_ * Tt_ * Hh_];   // (B, T, H)
// W split into bf16 hi/lo, stored TRANSPOSED: [n][k]
__device__ __nv_bfloat16 g_wxh_hi[256 * 256];
__device__ __nv_bfloat16 g_wxh_lo[256 * 256];
__device__ __nv_bfloat16 g_why_hi[256 * 256];
__device__ __nv_bfloat16 g_why_lo[256 * 256];

// ---------------------------------------------------------------------------
// helpers
// ---------------------------------------------------------------------------
__device__ __forceinline__ uint32_t smem_u32(const void* p) {
    uint32_t a;
    asm("{ .reg .u64 t; cvta.to.shared.u64 t, %1; cvt.u32.u64 %0, t; }"
        : "=r"(a) : "l"(p));
    return a;
}
__device__ __forceinline__ void mbar_init(uint32_t addr, uint32_t cnt) {
    asm volatile("mbarrier.init.shared.b64 [%0], %1;" :: "r"(addr), "r"(cnt) : "memory");
}

// ---------------------------------------------------------------------------
// Weight split kernel: W (K=256,N=256) fp32 -> transposed bf16 hi/lo [n][k]
// ---------------------------------------------------------------------------
__global__ void conv_w(const float* __restrict__ W,
                       __nv_bfloat16* __restrict__ hi,
                       __nv_bfloat16* __restrict__ lo)
{
    int k = blockIdx.x;
    int n = threadIdx.x;
    float w = W[k * 256 + n];
    __nv_bfloat16 h = __float2bfloat16(w);
    hi[n * 256 + k] = h;
    lo[n * 256 + k] = __float2bfloat16(w - __bfloat162float(h));
}

// ---------------------------------------------------------------------------
// Tensor-core GEMM via mma.sync m16n8k16 bf16 (sm_80-compatible PTX),
// fp32 emulated as bf16x3: A@W = Ahi@Whi + Ahi@Wlo + Alo@Whi.
// CTA: 128 rows x 128 cols, 8 warps (4 row x 2 col), warp tile 32x64.
// K chunked by 64 through smem; rows padded to 72 bf16 (conflict-free frags).
// mode 0: C[row*256 + n];  mode 1: C[((row%T)*B + row/T)*256 + n]
// ---------------------------------------------------------------------------
#define GSM_AHI  0
#define GSM_ALO  18432
#define GSM_WHI  36864
#define GSM_WLO  55296
#define GSM_BIAS 73728
#define GEMM_SMEM 74240

#define MMA16816(d, a, b0, b1) \
    asm volatile( \
        "mma.sync.aligned.m16n8k16.row.col.f32.bf16.bf16.f32 " \
        "{%0,%1,%2,%3}, {%4,%5,%6,%7}, {%8,%9}, {%0,%1,%2,%3};" \
        : "+f"((d)[0]), "+f"((d)[1]), "+f"((d)[2]), "+f"((d)[3]) \
        : "r"((a)[0]), "r"((a)[1]), "r"((a)[2]), "r"((a)[3]), \
          "r"(b0), "r"(b1))

__global__ void __launch_bounds__(256) gemm_mma(
    const float* __restrict__ A,
    const __nv_bfloat16* __restrict__ Whi_g,
    const __nv_bfloat16* __restrict__ Wlo_g,
    const float* __restrict__ bias,
    float* __restrict__ C, int mode)
{
    extern __shared__ char sm[];
    __nv_bfloat16* sAhi = (__nv_bfloat16*)(sm + GSM_AHI);   // [128][72]
    __nv_bfloat16* sAlo = (__nv_bfloat16*)(sm + GSM_ALO);
    __nv_bfloat16* sWhi = (__nv_bfloat16*)(sm + GSM_WHI);   // [128][72]
    __nv_bfloat16* sWlo = (__nv_bfloat16*)(sm + GSM_WLO);
    float* sBias = (float*)(sm + GSM_BIAS);                  // [128]

    const int tid  = threadIdx.x;
    const int wid  = tid >> 5;
    const int lane = tid & 31;
    const int rowTile = blockIdx.y;
    const int colTile = blockIdx.x;

    const int wr = wid & 3;          // warp row group (32 rows)
    const int wc = wid >> 2;         // warp col group (64 cols)
    const int g   = lane >> 2;
    const int tig = lane & 3;

    const float* Ab = A + (size_t)rowTile * 128 * 256;

    if (tid < 128) sBias[tid] = bias[colTile * 128 + tid];

    float d[16][4];                  // [mt*8+nt][4]
#pragma unroll
    for (int i = 0; i < 16; i++)
#pragma unroll
        for (int q = 0; q < 4; q++) d[i][q] = 0.f;

    for (int kc = 0; kc < 4; kc++) {
        __syncthreads();             // previous chunk's frags consumed

        // ---- A chunk: 128 rows x 64 k fp32 -> bf16 hi/lo ----
#pragma unroll
        for (int i = 0; i < 8; i++) {
            int lin = i * 256 + tid;         // float4 index (2048)
            int row = lin >> 4;
            int kv  = lin & 15;
            float4 v = *(const float4*)(Ab + (size_t)row * 256 + kc * 64 + kv * 4);
            __nv_bfloat16 h0 = __float2bfloat16(v.x);
            __nv_bfloat16 h1 = __float2bfloat16(v.y);
            __nv_bfloat16 h2 = __float2bfloat16(v.z);
            __nv_bfloat16 h3 = __float2bfloat16(v.w);
            __nv_bfloat16 l0 = __float2bfloat16(v.x - __bfloat162float(h0));
            __nv_bfloat16 l1 = __float2bfloat16(v.y - __bfloat162float(h1));
            __nv_bfloat16 l2 = __float2bfloat16(v.z - __bfloat162float(h2));
            __nv_bfloat16 l3 = __float2bfloat16(v.w - __bfloat162float(h3));
            int o = row * 72 + kv * 4;
            *(__nv_bfloat162*)(sAhi + o)     = __nv_bfloat162(h0, h1);
            *(__nv_bfloat162*)(sAhi + o + 2) = __nv_bfloat162(h2, h3);
            *(__nv_bfloat162*)(sAlo + o)     = __nv_bfloat162(l0, l1);
            *(__nv_bfloat162*)(sAlo + o + 2) = __nv_bfloat162(l2, l3);
        }

        // ---- W chunk: 128 n-rows x 64 k bf16 hi/lo ----
#pragma unroll
        for (int i = 0; i < 4; i++) {
            int lin = i * 256 + tid;         // uint4 index (1024)
            int n  = lin >> 3;
            int k8 = lin & 7;
            size_t go = (size_t)(colTile * 128 + n) * 256 + kc * 64 + k8 * 8;
            uint4 vh = *(const uint4*)(Whi_g + go);
            uint4 vl = *(const uint4*)(Wlo_g + go);
            *(uint4*)(sWhi + n * 72 + k8 * 8) = vh;
            *(uint4*)(sWlo + n * 72 + k8 * 8) = vl;
        }
        __syncthreads();

        // ---- compute: 4 k-steps of 16 ----
#pragma unroll
        for (int ks = 0; ks < 4; ks++) {
            const int kb = ks * 16;
            uint32_t ahi[2][4], alo[2][4];
#pragma unroll
            for (int mt = 0; mt < 2; mt++) {
                int rb = wr * 32 + mt * 16;
                int o00 = (rb + g) * 72 + kb + 2 * tig;
                int o10 = (rb + g + 8) * 72 + kb + 2 * tig;
                ahi[mt][0] = *(const uint32_t*)(sAhi + o00);
                ahi[mt][1] = *(const uint32_t*)(sAhi + o10);
                ahi[mt][2] = *(const uint32_t*)(sAhi + o00 + 8);
                ahi[mt][3] = *(const uint32_t*)(sAhi + o10 + 8);
                alo[mt][0] = *(const uint32_t*)(sAlo + o00);
                alo[mt][1] = *(const uint32_t*)(sAlo + o10);
                alo[mt][2] = *(const uint32_t*)(sAlo + o00 + 8);
                alo[mt][3] = *(const uint32_t*)(sAlo + o10 + 8);
            }
#pragma unroll
            for (int nt = 0; nt < 8; nt++) {
                int cb = wc * 64 + nt * 8;
                int ob = (cb + g) * 72 + kb + 2 * tig;
                uint32_t bh0 = *(const uint32_t*)(sWhi + ob);
                uint32_t bh1 = *(const uint32_t*)(sWhi + ob + 8);
                uint32_t bl0 = *(const uint32_t*)(sWlo + ob);
                uint32_t bl1 = *(const uint32_t*)(sWlo + ob + 8);
#pragma unroll
                for (int mt = 0; mt < 2; mt++) {
                    MMA16816(d[mt * 8 + nt], ahi[mt], bh0, bh1);
                    MMA16816(d[mt * 8 + nt], ahi[mt], bl0, bl1);
                    MMA16816(d[mt * 8 + nt], alo[mt], bh0, bh1);
                }
            }
        }
    }

    // ---- epilogue: direct stores (32B sectors per row, fully used) ----
#pragma unroll
    for (int mt = 0; mt < 2; mt++) {
        long r0 = (long)rowTile * 128 + wr * 32 + mt * 16 + g;
        long r1 = r0 + 8;
        size_t off0, off1;
        if (mode == 0) {
            off0 = (size_t)r0 * 256;
            off1 = (size_t)r1 * 256;
        } else {
            off0 = ((size_t)(r0 % Tt_) * Bb_ + (r0 / Tt_)) * 256;
            off1 = ((size_t)(r1 % Tt_) * Bb_ + (r1 / Tt_)) * 256;
        }
#pragma unroll
        for (int nt = 0; nt < 8; nt++) {
            int lc  = wc * 64 + nt * 8 + 2 * tig;      // local col 0..127
            int gc  = colTile * 128 + lc;              // global col
            float b0 = sBias[lc], b1 = sBias[lc + 1];
            float* p0 = C + off0 + gc;
            float* p1 = C + off1 + gc;
            float2 v0 = make_float2(d[mt * 8 + nt][0] + b0, d[mt * 8 + nt][1] + b1);
            float2 v1 = make_float2(d[mt * 8 + nt][2] + b0, d[mt * 8 + nt][3] + b1);
            *(float2*)p0 = v0;
            *(float2*)p1 = v1;
        }
    }
}

// ---------------------------------------------------------------------------
// K-split cluster scan (unchanged from round 5 — known good).
// ---------------------------------------------------------------------------
#define FMA2(acc, h, w) \
    asm("fma.rn.f32x2 %0, %1, %2, %0;" : "+l"(acc) : "l"(h), "l"(w))

__device__ __forceinline__ unsigned long long pack2(float lo, float hi) {
    unsigned long long v;
    asm("mov.b64 %0, {%1, %2};" : "=l"(v) : "f"(lo), "f"(hi));
    return v;
}
__device__ __forceinline__ float sum2(unsigned long long v) {
    float lo, hi;
    asm("mov.b64 {%0, %1}, %2;" : "=f"(lo), "=f"(hi) : "l"(v));
    return lo + hi;
}
__device__ __forceinline__ uint32_t mapa_u32(uint32_t laddr, uint32_t peer) {
    uint32_t r;
    asm("mapa.shared::cluster.u32 %0, %1, %2;" : "=r"(r) : "r"(laddr), "r"(peer));
    return r;
}
__device__ __forceinline__ void mbar_expect_tx(uint32_t addr, uint32_t bytes) {
    asm volatile("mbarrier.arrive.expect_tx.shared.b64 _, [%0], %1;"
                 :: "r"(addr), "r"(bytes) : "memory");
}
__device__ __forceinline__ void st_async_f32(uint32_t raddr, float v, uint32_t rbar) {
    asm volatile(
        "st.async.shared::cluster.mbarrier::complete_tx::bytes.b32 [%0], %1, [%2];"
        :: "r"(raddr), "r"(__float_as_uint(v)), "r"(rbar) : "memory");
}
__device__ __forceinline__ void mbar_wait_cluster(uint32_t addr, uint32_t parity) {
    asm volatile(
        "{\n\t"
        ".reg .pred P;\n\t"
        "WL%=:\n\t"
        "mbarrier.try_wait.parity.acquire.cluster.shared::cta.b64 P, [%0], %1, 0x989680;\n\t"
        "@P bra WD%=;\n\t"
        "bra WL%=;\n\t"
        "WD%=:\n\t"
        "}" :: "r"(addr), "r"(parity) : "memory");
}

__global__ void __launch_bounds__(256, 1) __cluster_dims__(2, 1, 1)
rnn_scan_ksplit(
    const float* __restrict__ xp,   // (T, B, H)
    const float* __restrict__ Whh,  // (H, H) [k][j]
    const float* __restrict__ h0,   // (B, H)
    float* __restrict__ hs,         // (B, T, H)
    float* __restrict__ hfin)       // (B, H)
{
    __shared__ float hbuf[2][128];
    __shared__ float rbuf[2][128];
    __shared__ __align__(8) unsigned long long bar[2];

    const int b   = blockIdx.x >> 1;
    const int r   = blockIdx.x & 1;
    const int tid = threadIdx.x;
    const int c   = tid;
    const int ci  = c & 127;
    const bool own = ((c >> 7) == r);
    const int kbase = r * 128;

    const uint32_t u_bar0 = smem_u32(&bar[0]);
    const uint32_t u_bar1 = smem_u32(&bar[1]);
    const uint32_t u_rbuf = smem_u32(&rbuf[0][0]);
    const uint32_t peer   = (uint32_t)(1 - r);
    const uint32_t ru_rbuf = mapa_u32(u_rbuf, peer);
    const uint32_t ru_bar0 = mapa_u32(u_bar0, peer);
    const uint32_t ru_bar1 = mapa_u32(u_bar1, peer);

    if (tid == 0) {
        mbar_init(u_bar0, 1);
        mbar_init(u_bar1, 1);
        mbar_expect_tx(u_bar0, 128 * 4);
        mbar_expect_tx(u_bar1, 128 * 4);
    }

    unsigned long long wr[64];
#pragma unroll
    for (int p = 0; p < 64; p++) {
        int k = kbase + 2 * p;
        wr[p] = pack2(Whh[(size_t)k * Hh_ + c], Whh[(size_t)(k + 1) * Hh_ + c]);
    }

    if (tid < 128) hbuf[0][tid] = h0[b * Hh_ + kbase + tid];
    __syncthreads();
    asm volatile("barrier.cluster.arrive.aligned;" ::: "memory");
    asm volatile("barrier.cluster.wait.aligned;"   ::: "memory");

    float xpc = 0.f, xpn = 0.f;
    if (own) {
        xpc = __ldcs(&xp[((size_t)0 * Bb_ + b) * Hh_ + c]);
        xpn = __ldcs(&xp[((size_t)1 * Bb_ + b) * Hh_ + c]);
    }

    const size_t hs_base = ((size_t)b * Tt_) * Hh_ + c;
    float hlast = 0.f;

    for (int t = 0; t < Tt_; t++) {
        const int pb = t & 1;
        const int nb = pb ^ 1;

        const ulonglong2* h2 = (const ulonglong2*)(&hbuf[pb][0]);
        unsigned long long a0 = 0ull, a1 = 0ull, a2 = 0ull, a3 = 0ull;
#pragma unroll
        for (int q = 0; q < 16; q++) {
            ulonglong2 hv0 = h2[2 * q];
            ulonglong2 hv1 = h2[2 * q + 1];
            FMA2(a0, hv0.x, wr[4 * q + 0]);
            FMA2(a1, hv0.y, wr[4 * q + 1]);
            FMA2(a2, hv1.x, wr[4 * q + 2]);
            FMA2(a3, hv1.y, wr[4 * q + 3]);
        }
        float part = (sum2(a0) + sum2(a1)) + (sum2(a2) + sum2(a3));

        if (!own) {
            uint32_t rb = (pb == 0) ? ru_bar0 : ru_bar1;
            st_async_f32(ru_rbuf + (uint32_t)(pb * 128 + ci) * 4u, part, rb);
        } else {
            uint32_t ub = (pb == 0) ? u_bar0 : u_bar1;
            mbar_wait_cluster(ub, (t >> 1) & 1);
            if (ci == 0 && t + 2 < Tt_) mbar_expect_tx(ub, 128 * 4);

            float h = tanhf(part + rbuf[pb][ci] + xpc);
            hs[hs_base + (size_t)t * Hh_] = h;
            hlast = h;
            hbuf[nb][ci] = h;

            xpc = xpn;
            if (t + 2 < Tt_)
                xpn = __ldcs(&xp[((size_t)(t + 2) * Bb_ + b) * Hh_ + c]);
        }
        __syncthreads();
    }

    if (own) hfin[b * Hh_ + c] = hlast;

    asm volatile("barrier.cluster.arrive.aligned;" ::: "memory");
    asm volatile("barrier.cluster.wait.aligned;"   ::: "memory");
}

// ---------------------------------------------------------------------------
// Launch
// ---------------------------------------------------------------------------
extern "C" void kernel_launch(void* const* d_in, const int* in_sizes, int n_in,
                              void* d_out, int out_size)
{
    const float* x    = (const float*)d_in[0];  // (B,T,D)
    const float* h0   = (const float*)d_in[1];  // (B,H)
    const float* W_xh = (const float*)d_in[2];  // (D,H)
    const float* W_hh = (const float*)d_in[3];  // (H,H)
    const float* b_h  = (const float*)d_in[4];  // (H)
    const float* W_hy = (const float*)d_in[5];  // (H,O)
    const float* b_y  = (const float*)d_in[6];  // (O)

    float* out  = (float*)d_out;                           // (B,T,O)
    float* hfin = out + (size_t)Bb_ * Tt_ * Oo_;           // (B,H)

    void *xp_ptr, *hs_ptr, *wxh_hi, *wxh_lo, *why_hi, *why_lo;
    cudaGetSymbolAddress(&xp_ptr, g_xp);
    cudaGetSymbolAddress(&hs_ptr, g_hs);
    cudaGetSymbolAddress(&wxh_hi, g_wxh_hi);
    cudaGetSymbolAddress(&wxh_lo, g_wxh_lo);
    cudaGetSymbolAddress(&why_hi, g_why_hi);
    cudaGetSymbolAddress(&why_lo, g_why_lo);

    cudaFuncSetAttribute(gemm_mma,
                         cudaFuncAttributeMaxDynamicSharedMemorySize, GEMM_SMEM);

    // 0) split weights into bf16 hi/lo (transposed)
    conv_w<<<256, 256>>>(W_xh, (__nv_bfloat16*)wxh_hi, (__nv_bfloat16*)wxh_lo);
    conv_w<<<256, 256>>>(W_hy, (__nv_bfloat16*)why_hi, (__nv_bfloat16*)why_lo);

    const int M = Bb_ * Tt_;            // 262144 rows
    dim3 gemmGrid(2, M / 128);

    // 1) xp = x @ W_xh + b_h   -> (T,B,H)
    gemm_mma<<<gemmGrid, 256, GEMM_SMEM>>>(
        x, (const __nv_bfloat16*)wxh_hi, (const __nv_bfloat16*)wxh_lo,
        b_h, (float*)xp_ptr, 1);

    // 2) k-split cluster scan -> hs (B,T,H), h_final
    rnn_scan_ksplit<<<2 * Bb_, 256>>>((const float*)xp_ptr, W_hh, h0,
                                      (float*)hs_ptr, hfin);

    // 3) out = hs @ W_hy + b_y -> (B,T,O)
    gemm_mma<<<gemmGrid, 256, GEMM_SMEM>>>(
        (const float*)hs_ptr, (const __nv_bfloat16*)why_hi,
        (const __nv_bfloat16*)why_lo, b_y, out, 0);
}